// round 11
// baseline (speedup 1.0000x reference)
#include <cuda_runtime.h>
#include <cstdint>

// ===========================================================================
// Fully fused single kernel: no device scratch, no second launch.
// Block = 2 points (p0, p0+1). 512 blocks, 256 threads.
//   Phase A: G[pt][i][h] = sum_j W2[h][i*32+j]*f[pt][j], W2 streamed through
//            smem (8 chunks x 8 h-rows, staged in the Us region), packed to
//            bf16 hi/mid fragment slots directly in smem.
//   Phase B: Ub (+b1), Bf, Us (= geo@W1, recomputed per block, [a][h] pitch 72)
//   Phase C: bf16 3-product m16n8k16 MMA mainloop (R8/R10 structure)
//   Phase D: smem-staged coalesced epilogue (+Bf)
// ===========================================================================

__device__ __forceinline__ uint32_t bf16x2_of(float lo, float hi) {
    uint32_t r;
    asm("cvt.rn.bf16x2.f32 %0, %1, %2;" : "=r"(r) : "f"(hi), "f"(lo));
    return r;
}
__device__ __forceinline__ float bf_lo(uint32_t p) { return __uint_as_float(p << 16); }
__device__ __forceinline__ float bf_hi(uint32_t p) { return __uint_as_float(p & 0xFFFF0000u); }

__device__ __forceinline__ void mma_bf16(float* c, uint32_t a0, uint32_t a1,
                                         uint32_t a2, uint32_t a3,
                                         uint32_t b0, uint32_t b1) {
    asm("mma.sync.aligned.m16n8k16.row.col.f32.bf16.bf16.f32 "
        "{%0,%1,%2,%3},{%4,%5,%6,%7},{%8,%9},{%0,%1,%2,%3};"
        : "+f"(c[0]), "+f"(c[1]), "+f"(c[2]), "+f"(c[3])
        : "r"(a0), "r"(a1), "r"(a2), "r"(a3), "r"(b0), "r"(b1));
}

#define U_P   72          // Us pitch (floats)
#define G_P32 40          // G fragment row pitch (u32)
#define ST_P  36          // epilogue stage pitch
#define W_P   36          // W2 stage i-pitch (floats)  -> conflict-free LDS.128
#define W_HP  (32 * W_P)  // 1152 floats per h-row
#define O_US  0           // 256*72 = 18432 (aliased: W2 stage 8*1152=9216; epi stage 128*36)
#define O_G0H 18432
#define O_G0M (O_G0H + 1280)
#define O_G1H (O_G0M + 1280)
#define O_G1M (O_G1H + 1280)
#define O_UB0 (O_G1M + 1280)
#define O_UB1 (O_UB0 + 64)
#define O_BF0 (O_UB1 + 64)
#define O_BF1 (O_BF0 + 32)
#define SMF   (O_BF1 + 32)   // 23744 floats = 94976 B

__global__ void __launch_bounds__(256, 2) fused_kernel(
    const float* __restrict__ feat, const float* __restrict__ geo,
    const float* __restrict__ W1, const float* __restrict__ b1,
    const float* __restrict__ W2, const float* __restrict__ b2,
    float* __restrict__ out) {
    extern __shared__ float sm[];
    int p0 = blockIdx.x * 2;
    int z = p0 >> 8, b0 = p0 & 255;
    int t = threadIdx.x, lane = t & 31, wid = t >> 5;
    int g = lane >> 2, tq = lane & 3;

    // ================= Phase A: G compute =================
    // thread -> (pt = t>>7, i = t&31, h2l = (t>>5)&3); chunk ch covers h2 = 4ch+h2l
    {
        int ptA = t >> 7, iA = t & 31, h2l = (t >> 5) & 3;
        float4 fr[8];
        {
            const float4* fp = (const float4*)(feat + (size_t)(p0 + ptA) * 32);
            #pragma unroll
            for (int j4 = 0; j4 < 8; ++j4) fr[j4] = fp[j4];
        }
        float* Wst = sm + O_US;
        int iS = t >> 3, jS = (t & 7) * 4;
        float4 pf[8];
        #pragma unroll
        for (int k = 0; k < 8; ++k)
            pf[k] = *(const float4*)(W2 + (size_t)k * 1024 + 4 * t);

        #pragma unroll
        for (int ch = 0; ch < 8; ++ch) {
            #pragma unroll
            for (int k = 0; k < 8; ++k)
                *(float4*)(Wst + k * W_HP + iS * W_P + jS) = pf[k];
            if (ch < 7) {
                #pragma unroll
                for (int k = 0; k < 8; ++k)
                    pf[k] = *(const float4*)(W2 + (size_t)(8 * (ch + 1) + k) * 1024 + 4 * t);
            }
            __syncthreads();
            float e0 = 0.f, e1 = 0.f;
            const float* w0 = Wst + (2 * h2l) * W_HP + iA * W_P;
            const float* w1 = w0 + W_HP;
            #pragma unroll
            for (int j4 = 0; j4 < 8; ++j4) {
                float4 a = *(const float4*)(w0 + 4 * j4);
                float4 b = *(const float4*)(w1 + 4 * j4);
                float4 f = fr[j4];
                e0 += a.x * f.x + a.y * f.y + a.z * f.z + a.w * f.w;
                e1 += b.x * f.x + b.y * f.y + b.z * f.z + b.w * f.w;
            }
            uint32_t ph = bf16x2_of(e0, e1);
            uint32_t pm = bf16x2_of(e0 - bf_lo(ph), e1 - bf_hi(ph));
            int h2 = 4 * ch + h2l;
            int slot = 2 * (4 * (h2 >> 3) + (h2 & 3)) + ((h2 >> 2) & 1);
            *((uint32_t*)(sm + (ptA ? O_G1H : O_G0H)) + iA * G_P32 + slot) = ph;
            *((uint32_t*)(sm + (ptA ? O_G1M : O_G0M)) + iA * G_P32 + slot) = pm;
            __syncthreads();
        }
    }

    // ================= Phase B: Ub, Bf, Us =================
    if (t < 128) {
        int pt = t >> 6, h = t & 63;
        int pp = p0 + pt;
        float gx = geo[pp * 3], gy = geo[pp * 3 + 1], gz = geo[pp * 3 + 2];
        sm[(pt ? O_UB1 : O_UB0) + h] =
            gx * W1[h] + gy * W1[64 + h] + gz * W1[128 + h] + b1[h];
    } else if (t < 192) {
        int pt = (t >> 5) & 1, i = t & 31;
        const float4* bw = (const float4*)(b2 + i * 32);
        const float4* fv = (const float4*)(feat + (size_t)(p0 + pt) * 32);
        float s = 0.f;
        #pragma unroll
        for (int j = 0; j < 8; ++j) {
            float4 w = bw[j], f = fv[j];
            s += w.x * f.x + w.y * f.y + w.z * f.z + w.w * f.w;
        }
        sm[(pt ? O_BF1 : O_BF0) + i] = s;
    }
    {   // Us row a = t (rotated h4 order -> conflict-free STS.128)
        int a = t;
        int pp = z * 256 + a;
        float gx = geo[pp * 3], gy = geo[pp * 3 + 1], gz = geo[pp * 3 + 2];
        #pragma unroll
        for (int k = 0; k < 16; ++k) {
            int h4 = (k + a) & 15;
            float4 wx = *(const float4*)(W1 + h4 * 4);
            float4 wy = *(const float4*)(W1 + 64 + h4 * 4);
            float4 wz = *(const float4*)(W1 + 128 + h4 * 4);
            float4 u;
            u.x = gx * wx.x + gy * wy.x + gz * wz.x;
            u.y = gx * wx.y + gy * wy.y + gz * wz.y;
            u.z = gx * wx.z + gy * wy.z + gz * wz.z;
            u.w = gx * wx.w + gy * wy.w + gz * wz.w;
            *(float4*)(sm + O_US + a * U_P + h4 * 4) = u;
        }
    }
    __syncthreads();

    // ================= Phase C: MMA mainloop =================
    float acc[2][2][4][4];
    #pragma unroll
    for (int pt = 0; pt < 2; ++pt)
        #pragma unroll
        for (int mi = 0; mi < 2; ++mi)
            #pragma unroll
            for (int n = 0; n < 4; ++n)
                acc[pt][mi][n][0] = acc[pt][mi][n][1] =
                acc[pt][mi][n][2] = acc[pt][mi][n][3] = 0.f;

    #pragma unroll
    for (int s = 0; s < 4; ++s) {
        int kb = 16 * s;
        float2 u01[2][4];
        #pragma unroll
        for (int mi = 0; mi < 2; ++mi) {
            #pragma unroll
            for (int j = 0; j < 4; ++j) {
                int row = wid * 32 + mi * 16 + g + (j & 1) * 8;
                int col = kb + 2 * tq + (j >> 1) * 8;
                u01[mi][j] = *(const float2*)(sm + O_US + row * U_P + col);
            }
        }
        #pragma unroll
        for (int pt = 0; pt < 2; ++pt) {
            const float* ub = sm + (pt ? O_UB1 : O_UB0);
            float2 ubL = *(const float2*)(ub + kb + 2 * tq);
            float2 ubH = *(const float2*)(ub + kb + 2 * tq + 8);
            uint32_t Ah[2][4], Am[2][4];
            #pragma unroll
            for (int mi = 0; mi < 2; ++mi) {
                #pragma unroll
                for (int j = 0; j < 4; ++j) {
                    float2 e = (j >> 1) ? ubH : ubL;
                    float h0 = fmaxf(e.x - u01[mi][j].x, 0.f);
                    float h1 = fmaxf(e.y - u01[mi][j].y, 0.f);
                    uint32_t ph = bf16x2_of(h0, h1);
                    Ah[mi][j] = ph;
                    Am[mi][j] = bf16x2_of(h0 - bf_lo(ph), h1 - bf_hi(ph));
                }
            }
            const uint32_t* Gh = (const uint32_t*)(sm + (pt ? O_G1H : O_G0H));
            const uint32_t* Gm = (const uint32_t*)(sm + (pt ? O_G1M : O_G0M));
            #pragma unroll
            for (int n = 0; n < 4; ++n) {
                int bi = (n * 8 + g) * G_P32 + (s * 4 + tq) * 2;
                uint2 bh = *(const uint2*)(Gh + bi);
                uint2 bm = *(const uint2*)(Gm + bi);
                #pragma unroll
                for (int mi = 0; mi < 2; ++mi) {
                    mma_bf16(acc[pt][mi][n], Ah[mi][0], Ah[mi][1], Ah[mi][2], Ah[mi][3], bh.x, bh.y);
                    mma_bf16(acc[pt][mi][n], Ah[mi][0], Ah[mi][1], Ah[mi][2], Ah[mi][3], bm.x, bm.y);
                    mma_bf16(acc[pt][mi][n], Am[mi][0], Am[mi][1], Am[mi][2], Am[mi][3], bh.x, bh.y);
                }
            }
        }
    }
    __syncthreads();   // Us dead -> reuse as epilogue stage

    // ================= Phase D: epilogue =================
    float* st = sm + O_US;
    #pragma unroll
    for (int pt = 0; pt < 2; ++pt) {
        #pragma unroll
        for (int mi = 0; mi < 2; ++mi) {
            int row = wid * 32 + mi * 16 + g;
            #pragma unroll
            for (int n = 0; n < 4; ++n) {
                int col = n * 8 + 2 * tq;
                float2 v0 = {acc[pt][mi][n][0], acc[pt][mi][n][1]};
                float2 v1 = {acc[pt][mi][n][2], acc[pt][mi][n][3]};
                *(float2*)(st + row * ST_P + col) = v0;
                *(float2*)(st + (row + 8) * ST_P + col) = v1;
            }
        }
        __syncthreads();
        const float* bfp = sm + (pt ? O_BF1 : O_BF0);
        int b = b0 + pt;
        #pragma unroll
        for (int it = 0; it < 4; ++it) {
            int idx = it * 256 + t;
            int row = idx >> 2, c4 = idx & 3;
            // 256 rows handled in two passes of 128 rows x 8 col4? keep 8-wide:
            (void)row; (void)c4;
        }
        #pragma unroll
        for (int it = 0; it < 8; ++it) {
            int idx = it * 256 + t;
            int row = idx >> 3, c4 = idx & 7;
            float4 v = *(const float4*)(st + row * ST_P + c4 * 4);
            float4 bf = *(const float4*)(bfp + c4 * 4);
            v.x += bf.x; v.y += bf.y; v.z += bf.z; v.w += bf.w;
            *(float4*)(out + (((size_t)(z * 256 + row)) * 256 + b) * 32 + c4 * 4) = v;
        }
        __syncthreads();
    }
}

// ===========================================================================
extern "C" void kernel_launch(void* const* d_in, const int* in_sizes, int n_in,
                              void* d_out, int out_size) {
    const float* feat = (const float*)d_in[0];
    const float* geo  = (const float*)d_in[1];
    const float* W1   = (const float*)d_in[2];
    const float* b1   = (const float*)d_in[3];
    const float* W2   = (const float*)d_in[4];
    const float* b2   = (const float*)d_in[5];
    float* out = (float*)d_out;

    cudaFuncSetAttribute(fused_kernel, cudaFuncAttributeMaxDynamicSharedMemorySize,
                         SMF * 4);
    fused_kernel<<<512, 256, SMF * 4>>>(feat, geo, W1, b1, W2, b2, out);
}

// round 13
// speedup vs baseline: 1.2177x; 1.2177x over previous
#include <cuda_runtime.h>
#include <cstdint>

#define NPTS 1024

// Scratch (no cudaMalloc allowed): ONLY the packed G fragments.
// layout: [p][i][32] u32, slot 2*(s*4+tq)+0 = b0(k2=8s+tq), +1 = b1(k2=8s+tq+4)
__device__ uint32_t g_Gph[NPTS * 32 * 32];
__device__ uint32_t g_Gpm[NPTS * 32 * 32];

// ===========================================================================
// helpers
// ===========================================================================
__device__ __forceinline__ uint32_t bf16x2_of(float lo, float hi) {
    uint32_t r;
    asm("cvt.rn.bf16x2.f32 %0, %1, %2;" : "=r"(r) : "f"(hi), "f"(lo));
    return r;
}
__device__ __forceinline__ float bf_lo(uint32_t p) { return __uint_as_float(p << 16); }
__device__ __forceinline__ float bf_hi(uint32_t p) { return __uint_as_float(p & 0xFFFF0000u); }

__device__ __forceinline__ void split_u64(unsigned long long v, uint32_t& ph, uint32_t& pm) {
    float lo = __uint_as_float((uint32_t)v);
    float hi = __uint_as_float((uint32_t)(v >> 32));
    ph = bf16x2_of(lo, hi);
    pm = bf16x2_of(lo - bf_lo(ph), hi - bf_hi(ph));
}

__device__ __forceinline__ void mma_bf16(float* c, uint32_t a0, uint32_t a1,
                                         uint32_t a2, uint32_t a3,
                                         uint32_t b0, uint32_t b1) {
    asm("mma.sync.aligned.m16n8k16.row.col.f32.bf16.bf16.f32 "
        "{%0,%1,%2,%3},{%4,%5,%6,%7},{%8,%9},{%0,%1,%2,%3};"
        : "+f"(c[0]), "+f"(c[1]), "+f"(c[2]), "+f"(c[3])
        : "r"(a0), "r"(a1), "r"(a2), "r"(a3), "r"(b0), "r"(b1));
}

// ===========================================================================
// pre_G (grid 64x8, 256 thr): G SGEMM only.
//   G[p][i][h] = sum_j W2[h][i*32+j] * feat[p][j] -> packed bf16 hi/mid,
//   interleaved via lane^8 shuffle, contiguous uint4 stores.
// Triggers programmatic launch of pair_kernel immediately.
// ===========================================================================
#define FS_PAD 33
__global__ void __launch_bounds__(256) pre_G(
    const float* __restrict__ feat, const float* __restrict__ W2) {
#if __CUDA_ARCH__ >= 900
    cudaTriggerProgrammaticLaunchCompletion();
#endif
    int bx = blockIdx.x, by = blockIdx.y;
    int t = threadIdx.x;

    int pbase = bx * 16;
    int i0g = by * 4;
    int pg = t & 7, eg = t >> 3;
    int p0 = pg * 2, e0 = eg * 8;

    __shared__ float Fs[16 * FS_PAD];
    __shared__ float Ws[32][264];

    {
        int idx = t;           // 512 entries: 16p x 32j, 2 per thread
        #pragma unroll
        for (int k = 0; k < 2; ++k) {
            int p = idx >> 5, j = idx & 31;
            Fs[p * FS_PAD + j] = feat[(size_t)(pbase + p) * 32 + j];
            idx += 256;
        }
    }
    {
        int lane = t & 31, w = t >> 5;
        int j4 = lane & 7, sub = lane >> 3;
        #pragma unroll
        for (int q = 0; q < 8; ++q) {
            int pidx = w * 32 + q * 4 + sub;
            int il = pidx >> 6, h = pidx & 63;
            float4 v = ((const float4*)W2)[((size_t)h * 1024 + (i0g + il) * 32) / 4 + j4];
            int e = il * 64 + h;
            Ws[j4 * 4 + 0][e] = v.x;
            Ws[j4 * 4 + 1][e] = v.y;
            Ws[j4 * 4 + 2][e] = v.z;
            Ws[j4 * 4 + 3][e] = v.w;
        }
    }
    __syncthreads();

    ulonglong2 acc[2][2];
    #pragma unroll
    for (int r = 0; r < 2; ++r) {
        acc[r][0].x = acc[r][0].y = 0ull;
        acc[r][1].x = acc[r][1].y = 0ull;
    }
    #pragma unroll 8
    for (int j = 0; j < 32; ++j) {
        ulonglong2 w0 = *(const ulonglong2*)&Ws[j][e0];
        ulonglong2 w1 = *(const ulonglong2*)&Ws[j][e0 + 4];
        #pragma unroll
        for (int r = 0; r < 2; ++r) {
            float f = Fs[(p0 + r) * FS_PAD + j];
            unsigned long long s;
            unsigned int fb = __float_as_uint(f);
            asm("mov.b64 %0, {%1, %1};" : "=l"(s) : "r"(fb));
            asm("fma.rn.f32x2 %0, %1, %2, %0;" : "+l"(acc[r][0].x) : "l"(s), "l"(w0.x));
            asm("fma.rn.f32x2 %0, %1, %2, %0;" : "+l"(acc[r][0].y) : "l"(s), "l"(w0.y));
            asm("fma.rn.f32x2 %0, %1, %2, %0;" : "+l"(acc[r][1].x) : "l"(s), "l"(w1.x));
            asm("fma.rn.f32x2 %0, %1, %2, %0;" : "+l"(acc[r][1].y) : "l"(s), "l"(w1.y));
        }
    }

    // epilogue: lane^8 shuffle to interleave (b0,b1), contiguous uint4 stores.
    int il = eg >> 3, i = i0g + il;
    int e7 = eg & 7;
    int s = e7 >> 1, half = e7 & 1;
    #pragma unroll
    for (int r = 0; r < 2; ++r) {
        int p = pbase + p0 + r;
        uint4 vh, vm;
        split_u64(acc[r][0].x, vh.x, vm.x);
        split_u64(acc[r][0].y, vh.y, vm.y);
        split_u64(acc[r][1].x, vh.z, vm.z);
        split_u64(acc[r][1].y, vh.w, vm.w);
        uint4 ph, pm;
        ph.x = __shfl_xor_sync(0xffffffffu, vh.x, 8);
        ph.y = __shfl_xor_sync(0xffffffffu, vh.y, 8);
        ph.z = __shfl_xor_sync(0xffffffffu, vh.z, 8);
        ph.w = __shfl_xor_sync(0xffffffffu, vh.w, 8);
        pm.x = __shfl_xor_sync(0xffffffffu, vm.x, 8);
        pm.y = __shfl_xor_sync(0xffffffffu, vm.y, 8);
        pm.z = __shfl_xor_sync(0xffffffffu, vm.z, 8);
        pm.w = __shfl_xor_sync(0xffffffffu, vm.w, 8);
        size_t o = ((size_t)p * 32 + i) * 32 + 8 * s;
        if (!half) {
            uint4 o1 = {vh.x, ph.x, vh.y, ph.y};
            uint4 o2 = {vh.z, ph.z, vh.w, ph.w};
            *(uint4*)(g_Gph + o) = o1;
            *(uint4*)(g_Gph + o + 4) = o2;
        } else {
            uint4 o1 = {pm.x, vm.x, pm.y, vm.y};
            uint4 o2 = {pm.z, vm.z, pm.w, vm.w};
            *(uint4*)(g_Gpm + o) = o1;
            *(uint4*)(g_Gpm + o + 4) = o2;
        }
    }
}

// ===========================================================================
// pair_kernel: R8 structure. Prelude (Us/Ub/Bf computed from raw inputs) is
// pre-independent and overlaps pre_G via PDL; griddepsync before G loads.
// ===========================================================================
#define U_P 72
#define G_P32 40
#define ST_P 36
#define O_US  0
#define O_G0H 18432
#define O_G0M (O_G0H + 1280)
#define O_G1H (O_G0M + 1280)
#define O_G1M (O_G1H + 1280)
#define O_UB0 (O_G1M + 1280)
#define O_UB1 (O_UB0 + 64)
#define O_BF0 (O_UB1 + 64)
#define O_BF1 (O_BF0 + 32)
#define SMF   (O_BF1 + 32)      // 23744 floats = 94976 B

__global__ void __launch_bounds__(256, 2) pair_kernel(
    const float* __restrict__ feat, const float* __restrict__ geo,
    const float* __restrict__ W1, const float* __restrict__ b1,
    const float* __restrict__ b2, float* __restrict__ out) {
    extern __shared__ float sm[];
    int p0 = blockIdx.x * 2;
    int z = p0 >> 8, b0 = p0 & 255;
    int t = threadIdx.x, lane = t & 31, wid = t >> 5;
    int g = lane >> 2, tq = lane & 3;

    // ---- PRELUDE (pre-independent): Us = geo@W1 [a][h] pitch 72; Ub; Bf ----
    {
        int a = t;
        int pp = z * 256 + a;
        float gx = geo[pp * 3], gy = geo[pp * 3 + 1], gz = geo[pp * 3 + 2];
        #pragma unroll
        for (int k = 0; k < 16; ++k) {
            float4 wx = *(const float4*)(W1 + k * 4);
            float4 wy = *(const float4*)(W1 + 64 + k * 4);
            float4 wz = *(const float4*)(W1 + 128 + k * 4);
            float4 u;
            u.x = gx * wx.x + gy * wy.x + gz * wz.x;
            u.y = gx * wx.y + gy * wy.y + gz * wz.y;
            u.z = gx * wx.z + gy * wy.z + gz * wz.z;
            u.w = gx * wx.w + gy * wy.w + gz * wz.w;
            *(float4*)(sm + O_US + a * U_P + k * 4) = u;
        }
    }
    if (t < 128) {
        int pt = t >> 6, h = t & 63;
        int pp = p0 + pt;
        float gx = geo[pp * 3], gy = geo[pp * 3 + 1], gz = geo[pp * 3 + 2];
        sm[(pt ? O_UB1 : O_UB0) + h] =
            gx * W1[h] + gy * W1[64 + h] + gz * W1[128 + h] + b1[h];
    } else if (t < 192) {
        int pt = (t >> 5) & 1, i = t & 31;
        const float4* bw = (const float4*)(b2 + i * 32);
        const float4* fv = (const float4*)(feat + (size_t)(p0 + pt) * 32);
        float s = 0.f;
        #pragma unroll
        for (int j = 0; j < 8; ++j) {
            float4 w = bw[j], f = fv[j];
            s += w.x * f.x + w.y * f.y + w.z * f.z + w.w * f.w;
        }
        sm[(pt ? O_BF1 : O_BF0) + i] = s;
    }

    // ---- wait for pre_G, then load G fragments ----
#if __CUDA_ARCH__ >= 900
    cudaGridDependencySynchronize();
#endif
    {
        int i = t >> 3, c4 = (t & 7) * 4;
        size_t s0 = ((size_t)p0 * 32 + i) * 32 + c4;
        size_t s1 = ((size_t)(p0 + 1) * 32 + i) * 32 + c4;
        int d = i * G_P32 + c4;
        *(uint4*)((uint32_t*)(sm + O_G0H) + d) = *(const uint4*)(g_Gph + s0);
        *(uint4*)((uint32_t*)(sm + O_G0M) + d) = *(const uint4*)(g_Gpm + s0);
        *(uint4*)((uint32_t*)(sm + O_G1H) + d) = *(const uint4*)(g_Gph + s1);
        *(uint4*)((uint32_t*)(sm + O_G1M) + d) = *(const uint4*)(g_Gpm + s1);
    }
    __syncthreads();

    float acc[2][2][4][4];
    #pragma unroll
    for (int pt = 0; pt < 2; ++pt)
        #pragma unroll
        for (int mi = 0; mi < 2; ++mi)
            #pragma unroll
            for (int n = 0; n < 4; ++n)
                acc[pt][mi][n][0] = acc[pt][mi][n][1] =
                acc[pt][mi][n][2] = acc[pt][mi][n][3] = 0.f;

    // ---- mainloop: 4 k16 steps ----
    #pragma unroll
    for (int s = 0; s < 4; ++s) {
        int kb = 16 * s;
        float2 u01[2][4];
        #pragma unroll
        for (int mi = 0; mi < 2; ++mi) {
            #pragma unroll
            for (int j = 0; j < 4; ++j) {
                int row = wid * 32 + mi * 16 + g + (j & 1) * 8;
                int col = kb + 2 * tq + (j >> 1) * 8;
                u01[mi][j] = *(const float2*)(sm + O_US + row * U_P + col);
            }
        }
        #pragma unroll
        for (int pt = 0; pt < 2; ++pt) {
            const float* ub = sm + (pt ? O_UB1 : O_UB0);
            float2 ubL = *(const float2*)(ub + kb + 2 * tq);
            float2 ubH = *(const float2*)(ub + kb + 2 * tq + 8);
            uint32_t Ah[2][4], Am[2][4];
            #pragma unroll
            for (int mi = 0; mi < 2; ++mi) {
                #pragma unroll
                for (int j = 0; j < 4; ++j) {
                    float2 e = (j >> 1) ? ubH : ubL;
                    float h0 = fmaxf(e.x - u01[mi][j].x, 0.f);
                    float h1 = fmaxf(e.y - u01[mi][j].y, 0.f);
                    uint32_t ph = bf16x2_of(h0, h1);
                    Ah[mi][j] = ph;
                    Am[mi][j] = bf16x2_of(h0 - bf_lo(ph), h1 - bf_hi(ph));
                }
            }
            const uint32_t* Gh = (const uint32_t*)(sm + (pt ? O_G1H : O_G0H));
            const uint32_t* Gm = (const uint32_t*)(sm + (pt ? O_G1M : O_G0M));
            #pragma unroll
            for (int n = 0; n < 4; ++n) {
                int bi = (n * 8 + g) * G_P32 + (s * 4 + tq) * 2;
                uint2 bh = *(const uint2*)(Gh + bi);
                uint2 bm = *(const uint2*)(Gm + bi);
                #pragma unroll
                for (int mi = 0; mi < 2; ++mi) {
                    mma_bf16(acc[pt][mi][n], Ah[mi][0], Ah[mi][1], Ah[mi][2], Ah[mi][3], bh.x, bh.y);
                    mma_bf16(acc[pt][mi][n], Ah[mi][0], Ah[mi][1], Ah[mi][2], Ah[mi][3], bm.x, bm.y);
                    mma_bf16(acc[pt][mi][n], Am[mi][0], Am[mi][1], Am[mi][2], Am[mi][3], bh.x, bh.y);
                }
            }
        }
    }
    __syncthreads();   // Us dead -> reuse as stage

    // ---- epilogue per point: stage -> +Bf -> coalesced STG.128 ----
    float* st = sm + O_US;
    #pragma unroll
    for (int pt = 0; pt < 2; ++pt) {
        #pragma unroll
        for (int mi = 0; mi < 2; ++mi) {
            int row = wid * 32 + mi * 16 + g;
            #pragma unroll
            for (int n = 0; n < 4; ++n) {
                int col = n * 8 + 2 * tq;
                float2 v0 = {acc[pt][mi][n][0], acc[pt][mi][n][1]};
                float2 v1 = {acc[pt][mi][n][2], acc[pt][mi][n][3]};
                *(float2*)(st + row * ST_P + col) = v0;
                *(float2*)(st + (row + 8) * ST_P + col) = v1;
            }
        }
        __syncthreads();
        const float* bfp = sm + (pt ? O_BF1 : O_BF0);
        int b = b0 + pt;
        #pragma unroll
        for (int it = 0; it < 8; ++it) {
            int idx = it * 256 + t;
            int row = idx >> 3, c4 = idx & 7;
            float4 v = *(const float4*)(st + row * ST_P + c4 * 4);
            float4 bf = *(const float4*)(bfp + c4 * 4);
            v.x += bf.x; v.y += bf.y; v.z += bf.z; v.w += bf.w;
            *(float4*)(out + (((size_t)(z * 256 + row)) * 256 + b) * 32 + c4 * 4) = v;
        }
        __syncthreads();
    }
}

// ===========================================================================
extern "C" void kernel_launch(void* const* d_in, const int* in_sizes, int n_in,
                              void* d_out, int out_size) {
    const float* feat = (const float*)d_in[0];
    const float* geo  = (const float*)d_in[1];
    const float* W1   = (const float*)d_in[2];
    const float* b1   = (const float*)d_in[3];
    const float* W2   = (const float*)d_in[4];
    const float* b2   = (const float*)d_in[5];
    float* out = (float*)d_out;

    cudaFuncSetAttribute(pair_kernel, cudaFuncAttributeMaxDynamicSharedMemorySize,
                         SMF * 4);

    pre_G<<<dim3(64, 8), 256>>>(feat, W2);

    // PDL launch: pair's prelude overlaps pre_G; fallback to plain launch.
    cudaLaunchConfig_t cfg = {};
    cfg.gridDim = dim3(512);
    cfg.blockDim = dim3(256);
    cfg.dynamicSmemBytes = SMF * 4;
    cfg.stream = 0;
    cudaLaunchAttribute at[1];
    at[0].id = cudaLaunchAttributeProgrammaticStreamSerialization;
    at[0].val.programmaticStreamSerializationAllowed = 1;
    cfg.attrs = at;
    cfg.numAttrs = 1;
    cudaError_t err = cudaLaunchKernelEx(&cfg, pair_kernel,
                                         feat, geo, W1, b1, b2, out);
    if (err != cudaSuccess) {
        pair_kernel<<<512, 256, SMF * 4>>>(feat, geo, W1, b1, b2, out);
    }
}

// round 14
// speedup vs baseline: 1.5719x; 1.2909x over previous
#include <cuda_runtime.h>
#include <cstdint>

#define NPTS 1024

// Scratch: packed fp16x2 G fragments, interleaved [p][i][32] u32.
// slot 2*(s*4+tq)+0 = b0 (k2 = 8s+tq), slot 2*(s*4+tq)+1 = b1 (k2 = 8s+tq+4)
__device__ uint32_t g_Gp[NPTS * 32 * 32];

// ===========================================================================
// helpers
// ===========================================================================
__device__ __forceinline__ uint32_t f16x2_of(float lo, float hi) {
    uint32_t r;
    asm("cvt.rn.f16x2.f32 %0, %1, %2;" : "=r"(r) : "f"(hi), "f"(lo));
    return r;
}

__device__ __forceinline__ void mma_f16(float* c, uint32_t a0, uint32_t a1,
                                        uint32_t a2, uint32_t a3,
                                        uint32_t b0, uint32_t b1) {
    asm("mma.sync.aligned.m16n8k16.row.col.f32.f16.f16.f32 "
        "{%0,%1,%2,%3},{%4,%5,%6,%7},{%8,%9},{%0,%1,%2,%3};"
        : "+f"(c[0]), "+f"(c[1]), "+f"(c[2]), "+f"(c[3])
        : "r"(a0), "r"(a1), "r"(a2), "r"(a3), "r"(b0), "r"(b1));
}

// ===========================================================================
// pre_G (grid 16x8, 256 thr): G[p][i][h] = sum_j W2[h][i*32+j]*feat[p][j]
// Block tile 64p x 256e (e = il*64 + h), thread tile 8p x 8e.
// Epilogue: fp16x2 pack + lane^8 shuffle interleave -> 1 uint4 store per r.
// ===========================================================================
#define FS_PAD 33
__global__ void __launch_bounds__(256) pre_G(
    const float* __restrict__ feat, const float* __restrict__ W2) {
    int bx = blockIdx.x, by = blockIdx.y;
    int t = threadIdx.x;

    int pbase = bx * 64;
    int i0g = by * 4;
    int pg = t & 7, eg = t >> 3;
    int p0 = pg * 8, e0 = eg * 8;

    __shared__ float Fs[64 * FS_PAD];
    __shared__ float Ws[32][264];

    #pragma unroll
    for (int k = 0; k < 8; ++k) {
        int idx = t + k * 256;
        int p = idx >> 5, j = idx & 31;
        Fs[p * FS_PAD + j] = feat[(size_t)(pbase + p) * 32 + j];
    }
    {
        int lane = t & 31, w = t >> 5;
        int j4 = lane & 7, sub = lane >> 3;
        #pragma unroll
        for (int q = 0; q < 8; ++q) {
            int pidx = w * 32 + q * 4 + sub;
            int il = pidx >> 6, h = pidx & 63;
            float4 v = ((const float4*)W2)[((size_t)h * 1024 + (i0g + il) * 32) / 4 + j4];
            int e = il * 64 + h;
            Ws[j4 * 4 + 0][e] = v.x;
            Ws[j4 * 4 + 1][e] = v.y;
            Ws[j4 * 4 + 2][e] = v.z;
            Ws[j4 * 4 + 3][e] = v.w;
        }
    }
    __syncthreads();

    ulonglong2 acc[8][2];
    #pragma unroll
    for (int r = 0; r < 8; ++r) {
        acc[r][0].x = acc[r][0].y = 0ull;
        acc[r][1].x = acc[r][1].y = 0ull;
    }
    #pragma unroll 8
    for (int j = 0; j < 32; ++j) {
        ulonglong2 w0 = *(const ulonglong2*)&Ws[j][e0];
        ulonglong2 w1 = *(const ulonglong2*)&Ws[j][e0 + 4];
        #pragma unroll
        for (int r = 0; r < 8; ++r) {
            float f = Fs[(p0 + r) * FS_PAD + j];
            unsigned long long s;
            unsigned int fb = __float_as_uint(f);
            asm("mov.b64 %0, {%1, %1};" : "=l"(s) : "r"(fb));
            asm("fma.rn.f32x2 %0, %1, %2, %0;" : "+l"(acc[r][0].x) : "l"(s), "l"(w0.x));
            asm("fma.rn.f32x2 %0, %1, %2, %0;" : "+l"(acc[r][0].y) : "l"(s), "l"(w0.y));
            asm("fma.rn.f32x2 %0, %1, %2, %0;" : "+l"(acc[r][1].x) : "l"(s), "l"(w1.x));
            asm("fma.rn.f32x2 %0, %1, %2, %0;" : "+l"(acc[r][1].y) : "l"(s), "l"(w1.y));
        }
    }

    // epilogue: e0 = eg*8 covers k2 = 4*(eg&7)..+3 for i = i0g + (eg>>3).
    // s = (eg&7)>>1, half = eg&1. lane^8 partner = other half, same (i, s, p's).
    int i = i0g + (eg >> 3);
    int s = (eg & 7) >> 1, half = eg & 1;
    #pragma unroll
    for (int r = 0; r < 8; ++r) {
        int p = pbase + p0 + r;
        uint4 vh;
        {
            float lo, hi;
            lo = __uint_as_float((uint32_t)acc[r][0].x);
            hi = __uint_as_float((uint32_t)(acc[r][0].x >> 32));
            vh.x = f16x2_of(lo, hi);
            lo = __uint_as_float((uint32_t)acc[r][0].y);
            hi = __uint_as_float((uint32_t)(acc[r][0].y >> 32));
            vh.y = f16x2_of(lo, hi);
            lo = __uint_as_float((uint32_t)acc[r][1].x);
            hi = __uint_as_float((uint32_t)(acc[r][1].x >> 32));
            vh.z = f16x2_of(lo, hi);
            lo = __uint_as_float((uint32_t)acc[r][1].y);
            hi = __uint_as_float((uint32_t)(acc[r][1].y >> 32));
            vh.w = f16x2_of(lo, hi);
        }
        uint4 pr;
        pr.x = __shfl_xor_sync(0xffffffffu, vh.x, 8);
        pr.y = __shfl_xor_sync(0xffffffffu, vh.y, 8);
        pr.z = __shfl_xor_sync(0xffffffffu, vh.z, 8);
        pr.w = __shfl_xor_sync(0xffffffffu, vh.w, 8);
        size_t o = ((size_t)p * 32 + i) * 32 + 8 * s;
        if (!half) {   // slots 8s..8s+3: {b0(q=4s), b1(q=4s), b0(q=4s+1), b1(q=4s+1)}
            uint4 w0 = {vh.x, pr.x, vh.y, pr.y};
            *(uint4*)(g_Gp + o) = w0;
        } else {       // slots 8s+4..8s+7
            uint4 w1 = {pr.z, vh.z, pr.w, vh.w};
            *(uint4*)(g_Gp + o + 4) = w1;
        }
    }
}

// ===========================================================================
// pair_kernel: single-product fp16 MMA, 2 points/block, 512 blocks, 256 thr.
// Us (geo@W1, [a][h] pitch 72) computed in-kernel; Ub/Bf likewise.
// ===========================================================================
#define U_P 72
#define G_P32 40
#define ST_P 36
#define O_US  0
#define O_G0  18432
#define O_G1  (O_G0 + 1280)
#define O_UB0 (O_G1 + 1280)
#define O_UB1 (O_UB0 + 64)
#define O_BF0 (O_UB1 + 64)
#define O_BF1 (O_BF0 + 32)
#define SMF   (O_BF1 + 32)      // 21184 floats = 84736 B

__global__ void __launch_bounds__(256, 2) pair_kernel(
    const float* __restrict__ feat, const float* __restrict__ geo,
    const float* __restrict__ W1, const float* __restrict__ b1,
    const float* __restrict__ b2, float* __restrict__ out) {
    extern __shared__ float sm[];
    int p0 = blockIdx.x * 2;
    int z = p0 >> 8, b0 = p0 & 255;
    int t = threadIdx.x, lane = t & 31, wid = t >> 5;
    int g = lane >> 2, tq = lane & 3;

    // ---- fills: Us (geo@W1), G fragments, Ub, Bf ----
    {
        int a = t;
        int pp = z * 256 + a;
        float gx = geo[pp * 3], gy = geo[pp * 3 + 1], gz = geo[pp * 3 + 2];
        #pragma unroll
        for (int k = 0; k < 16; ++k) {
            float4 wx = *(const float4*)(W1 + k * 4);
            float4 wy = *(const float4*)(W1 + 64 + k * 4);
            float4 wz = *(const float4*)(W1 + 128 + k * 4);
            float4 u;
            u.x = gx * wx.x + gy * wy.x + gz * wz.x;
            u.y = gx * wx.y + gy * wy.y + gz * wz.y;
            u.z = gx * wx.z + gy * wy.z + gz * wz.z;
            u.w = gx * wx.w + gy * wy.w + gz * wz.w;
            *(float4*)(sm + O_US + a * U_P + k * 4) = u;
        }
    }
    {
        int i = t >> 3, c4 = (t & 7) * 4;
        int d = i * G_P32 + c4;
        *(uint4*)((uint32_t*)(sm + O_G0) + d) =
            *(const uint4*)(g_Gp + ((size_t)p0 * 32 + i) * 32 + c4);
        *(uint4*)((uint32_t*)(sm + O_G1) + d) =
            *(const uint4*)(g_Gp + ((size_t)(p0 + 1) * 32 + i) * 32 + c4);
    }
    if (t < 128) {
        int pt = t >> 6, h = t & 63;
        int pp = p0 + pt;
        float gx = geo[pp * 3], gy = geo[pp * 3 + 1], gz = geo[pp * 3 + 2];
        sm[(pt ? O_UB1 : O_UB0) + h] =
            gx * W1[h] + gy * W1[64 + h] + gz * W1[128 + h] + b1[h];
    } else if (t < 192) {
        int pt = (t >> 5) & 1, i = t & 31;
        const float4* bw = (const float4*)(b2 + i * 32);
        const float4* fv = (const float4*)(feat + (size_t)(p0 + pt) * 32);
        float s = 0.f;
        #pragma unroll
        for (int j = 0; j < 8; ++j) {
            float4 w = bw[j], f = fv[j];
            s += w.x * f.x + w.y * f.y + w.z * f.z + w.w * f.w;
        }
        sm[(pt ? O_BF1 : O_BF0) + i] = s;
    }
    __syncthreads();

    float acc[2][2][4][4];
    #pragma unroll
    for (int pt = 0; pt < 2; ++pt)
        #pragma unroll
        for (int mi = 0; mi < 2; ++mi)
            #pragma unroll
            for (int n = 0; n < 4; ++n)
                acc[pt][mi][n][0] = acc[pt][mi][n][1] =
                acc[pt][mi][n][2] = acc[pt][mi][n][3] = 0.f;

    // ---- mainloop: 4 k16 steps, single fp16 product ----
    #pragma unroll
    for (int s = 0; s < 4; ++s) {
        int kb = 16 * s;
        float2 u01[2][4];
        #pragma unroll
        for (int mi = 0; mi < 2; ++mi) {
            #pragma unroll
            for (int j = 0; j < 4; ++j) {
                int row = wid * 32 + mi * 16 + g + (j & 1) * 8;
                int col = kb + 2 * tq + (j >> 1) * 8;
                u01[mi][j] = *(const float2*)(sm + O_US + row * U_P + col);
            }
        }
        #pragma unroll
        for (int pt = 0; pt < 2; ++pt) {
            const float* ub = sm + (pt ? O_UB1 : O_UB0);
            float2 ubL = *(const float2*)(ub + kb + 2 * tq);
            float2 ubH = *(const float2*)(ub + kb + 2 * tq + 8);
            uint32_t Ah[2][4];
            #pragma unroll
            for (int mi = 0; mi < 2; ++mi) {
                #pragma unroll
                for (int j = 0; j < 4; ++j) {
                    float2 e = (j >> 1) ? ubH : ubL;
                    float h0 = fmaxf(e.x - u01[mi][j].x, 0.f);
                    float h1 = fmaxf(e.y - u01[mi][j].y, 0.f);
                    Ah[mi][j] = f16x2_of(h0, h1);
                }
            }
            const uint32_t* Gp = (const uint32_t*)(sm + (pt ? O_G1 : O_G0));
            #pragma unroll
            for (int n = 0; n < 4; ++n) {
                uint2 bh = *(const uint2*)(Gp + (n * 8 + g) * G_P32 + (s * 4 + tq) * 2);
                #pragma unroll
                for (int mi = 0; mi < 2; ++mi)
                    mma_f16(acc[pt][mi][n], Ah[mi][0], Ah[mi][1], Ah[mi][2], Ah[mi][3],
                            bh.x, bh.y);
            }
        }
    }
    __syncthreads();   // Us dead -> reuse as stage

    // ---- epilogue per point: stage -> +Bf -> coalesced STG.128 ----
    float* st = sm + O_US;
    #pragma unroll
    for (int pt = 0; pt < 2; ++pt) {
        #pragma unroll
        for (int mi = 0; mi < 2; ++mi) {
            int row = wid * 32 + mi * 16 + g;
            #pragma unroll
            for (int n = 0; n < 4; ++n) {
                int col = n * 8 + 2 * tq;
                float2 v0 = {acc[pt][mi][n][0], acc[pt][mi][n][1]};
                float2 v1 = {acc[pt][mi][n][2], acc[pt][mi][n][3]};
                *(float2*)(st + row * ST_P + col) = v0;
                *(float2*)(st + (row + 8) * ST_P + col) = v1;
            }
        }
        __syncthreads();
        const float* bfp = sm + (pt ? O_BF1 : O_BF0);
        int b = b0 + pt;
        #pragma unroll
        for (int it = 0; it < 8; ++it) {
            int idx = it * 256 + t;
            int row = idx >> 3, c4 = idx & 7;
            float4 v = *(const float4*)(st + row * ST_P + c4 * 4);
            float4 bf = *(const float4*)(bfp + c4 * 4);
            v.x += bf.x; v.y += bf.y; v.z += bf.z; v.w += bf.w;
            *(float4*)(out + (((size_t)(z * 256 + row)) * 256 + b) * 32 + c4 * 4) = v;
        }
        __syncthreads();
    }
}

// ===========================================================================
extern "C" void kernel_launch(void* const* d_in, const int* in_sizes, int n_in,
                              void* d_out, int out_size) {
    const float* feat = (const float*)d_in[0];
    const float* geo  = (const float*)d_in[1];
    const float* W1   = (const float*)d_in[2];
    const float* b1   = (const float*)d_in[3];
    const float* W2   = (const float*)d_in[4];
    const float* b2   = (const float*)d_in[5];
    float* out = (float*)d_out;

    cudaFuncSetAttribute(pair_kernel, cudaFuncAttributeMaxDynamicSharedMemorySize,
                         SMF * 4);

    pre_G<<<dim3(16, 8), 256>>>(feat, W2);
    pair_kernel<<<512, 256, SMF * 4>>>(feat, geo, W1, b1, b2, out);
}

// round 16
// speedup vs baseline: 1.6907x; 1.0756x over previous
#include <cuda_runtime.h>
#include <cstdint>

#define NPTS 1024

// Scratch: packed fp16x2 G fragments, interleaved [p][i][32] u32.
// slot 2*(s*4+tq)+0 = b0 (k2 = 8s+tq), slot 2*(s*4+tq)+1 = b1 (k2 = 8s+tq+4)
__device__ uint32_t g_Gp[NPTS * 32 * 32];

// ===========================================================================
// helpers
// ===========================================================================
__device__ __forceinline__ uint32_t f16x2_of(float lo, float hi) {
    uint32_t r;
    asm("cvt.rn.f16x2.f32 %0, %1, %2;" : "=r"(r) : "f"(hi), "f"(lo));
    return r;
}
__device__ __forceinline__ uint32_t hsub2(uint32_t a, uint32_t b) {
    uint32_t r;
    asm("sub.rn.f16x2 %0, %1, %2;" : "=r"(r) : "r"(a), "r"(b));
    return r;
}
__device__ __forceinline__ uint32_t hmax2z(uint32_t a) {
    uint32_t r;
    asm("max.f16x2 %0, %1, %2;" : "=r"(r) : "r"(a), "r"(0u));
    return r;
}
__device__ __forceinline__ void mma_f16(float* c, uint32_t a0, uint32_t a1,
                                        uint32_t a2, uint32_t a3,
                                        uint32_t b0, uint32_t b1) {
    asm("mma.sync.aligned.m16n8k16.row.col.f32.f16.f16.f32 "
        "{%0,%1,%2,%3},{%4,%5,%6,%7},{%8,%9},{%0,%1,%2,%3};"
        : "+f"(c[0]), "+f"(c[1]), "+f"(c[2]), "+f"(c[3])
        : "r"(a0), "r"(a1), "r"(a2), "r"(a3), "r"(b0), "r"(b1));
}

// ===========================================================================
// pre_G (grid 32x8, 256 thr): G[p][i][h] = sum_j W2[h][i*32+j]*feat[p][j]
// Block tile 32p x 256e (e = il*64 + h), thread tile 4p x 8e.
// Epilogue: fp16x2 pack + lane^8 shuffle interleave -> contiguous uint4.
// ===========================================================================
#define FS_PAD 33
__global__ void __launch_bounds__(256) pre_G(
    const float* __restrict__ feat, const float* __restrict__ W2) {
    int bx = blockIdx.x, by = blockIdx.y;
    int t = threadIdx.x;

    int pbase = bx * 32;
    int i0g = by * 4;
    int pg = t & 7, eg = t >> 3;
    int p0 = pg * 4, e0 = eg * 8;

    __shared__ float Fs[32 * FS_PAD];
    __shared__ float Ws[32][264];

    #pragma unroll
    for (int k = 0; k < 4; ++k) {
        int idx = t + k * 256;
        int p = idx >> 5, j = idx & 31;
        Fs[p * FS_PAD + j] = feat[(size_t)(pbase + p) * 32 + j];
    }
    {
        int lane = t & 31, w = t >> 5;
        int j4 = lane & 7, sub = lane >> 3;
        #pragma unroll
        for (int q = 0; q < 8; ++q) {
            int pidx = w * 32 + q * 4 + sub;
            int il = pidx >> 6, h = pidx & 63;
            float4 v = ((const float4*)W2)[((size_t)h * 1024 + (i0g + il) * 32) / 4 + j4];
            int e = il * 64 + h;
            Ws[j4 * 4 + 0][e] = v.x;
            Ws[j4 * 4 + 1][e] = v.y;
            Ws[j4 * 4 + 2][e] = v.z;
            Ws[j4 * 4 + 3][e] = v.w;
        }
    }
    __syncthreads();

    ulonglong2 acc[4][2];
    #pragma unroll
    for (int r = 0; r < 4; ++r) {
        acc[r][0].x = acc[r][0].y = 0ull;
        acc[r][1].x = acc[r][1].y = 0ull;
    }
    #pragma unroll 8
    for (int j = 0; j < 32; ++j) {
        ulonglong2 w0 = *(const ulonglong2*)&Ws[j][e0];
        ulonglong2 w1 = *(const ulonglong2*)&Ws[j][e0 + 4];
        #pragma unroll
        for (int r = 0; r < 4; ++r) {
            float f = Fs[(p0 + r) * FS_PAD + j];
            unsigned long long s;
            unsigned int fb = __float_as_uint(f);
            asm("mov.b64 %0, {%1, %1};" : "=l"(s) : "r"(fb));
            asm("fma.rn.f32x2 %0, %1, %2, %0;" : "+l"(acc[r][0].x) : "l"(s), "l"(w0.x));
            asm("fma.rn.f32x2 %0, %1, %2, %0;" : "+l"(acc[r][0].y) : "l"(s), "l"(w0.y));
            asm("fma.rn.f32x2 %0, %1, %2, %0;" : "+l"(acc[r][1].x) : "l"(s), "l"(w1.x));
            asm("fma.rn.f32x2 %0, %1, %2, %0;" : "+l"(acc[r][1].y) : "l"(s), "l"(w1.y));
        }
    }

    // epilogue: i = i0g + (eg>>3); s = (eg&7)>>1; half = eg&1; partner = lane^8
    int i = i0g + (eg >> 3);
    int s = (eg & 7) >> 1, half = eg & 1;
    #pragma unroll
    for (int r = 0; r < 4; ++r) {
        int p = pbase + p0 + r;
        uint4 vh;
        {
            float lo, hi;
            lo = __uint_as_float((uint32_t)acc[r][0].x);
            hi = __uint_as_float((uint32_t)(acc[r][0].x >> 32));
            vh.x = f16x2_of(lo, hi);
            lo = __uint_as_float((uint32_t)acc[r][0].y);
            hi = __uint_as_float((uint32_t)(acc[r][0].y >> 32));
            vh.y = f16x2_of(lo, hi);
            lo = __uint_as_float((uint32_t)acc[r][1].x);
            hi = __uint_as_float((uint32_t)(acc[r][1].x >> 32));
            vh.z = f16x2_of(lo, hi);
            lo = __uint_as_float((uint32_t)acc[r][1].y);
            hi = __uint_as_float((uint32_t)(acc[r][1].y >> 32));
            vh.w = f16x2_of(lo, hi);
        }
        uint4 pr;
        pr.x = __shfl_xor_sync(0xffffffffu, vh.x, 8);
        pr.y = __shfl_xor_sync(0xffffffffu, vh.y, 8);
        pr.z = __shfl_xor_sync(0xffffffffu, vh.z, 8);
        pr.w = __shfl_xor_sync(0xffffffffu, vh.w, 8);
        size_t o = ((size_t)p * 32 + i) * 32 + 8 * s;
        if (!half) {
            uint4 w0 = {vh.x, pr.x, vh.y, pr.y};
            *(uint4*)(g_Gp + o) = w0;
        } else {
            uint4 w1 = {pr.z, vh.z, pr.w, vh.w};
            *(uint4*)(g_Gp + o + 4) = w1;
        }
    }
}

// ===========================================================================
// pair_kernel: 4 points/block, 512 threads (16 warps), 256 blocks.
// Us stored packed fp16x2 ([a][k2] pitch 36 u32) — A fragments shared by all
// 4 points; A-build = sub.rn.f16x2 + max.f16x2 from packed ub.
// ===========================================================================
#define U_P32 36
#define G_P32 40
#define ST_P  36
#define O_US  0                   // 256*36 = 9216 u32 (reused as fp32 stage)
#define O_G   9216                // 4*32*40 = 5120
#define O_UB  (O_G + 5120)        // 4*32 u32 (packed f16x2 ub)
#define O_BF  (O_UB + 128)        // 4*32 f32
#define SMF_U32 (O_BF + 128)      // 14592 u32 = 58368 B

__global__ void __launch_bounds__(512, 1) pair_kernel(
    const float* __restrict__ feat, const float* __restrict__ geo,
    const float* __restrict__ W1, const float* __restrict__ b1,
    const float* __restrict__ b2, float* __restrict__ out) {
    extern __shared__ uint32_t smu[];
    float* smf = (float*)smu;
    int p0 = blockIdx.x * 4;
    int z = p0 >> 8, b0 = p0 & 255;
    int t = threadIdx.x, lane = t & 31, wid = t >> 5;   // wid 0..15
    int g = lane >> 2, tq = lane & 3;

    // ---- Us16 fill: 256 rows x 8 uint4 (each = 8 h values packed f16x2) ----
    #pragma unroll
    for (int it = 0; it < 4; ++it) {
        int idx = it * 512 + t;
        int row = idx >> 3, c4 = idx & 7;
        int pp = z * 256 + row;
        float gx = geo[pp * 3], gy = geo[pp * 3 + 1], gz = geo[pp * 3 + 2];
        int h = c4 * 8;
        float u[8];
        #pragma unroll
        for (int q = 0; q < 2; ++q) {
            float4 wx = *(const float4*)(W1 + h + q * 4);
            float4 wy = *(const float4*)(W1 + 64 + h + q * 4);
            float4 wz = *(const float4*)(W1 + 128 + h + q * 4);
            u[q * 4 + 0] = gx * wx.x + gy * wy.x + gz * wz.x;
            u[q * 4 + 1] = gx * wx.y + gy * wy.y + gz * wz.y;
            u[q * 4 + 2] = gx * wx.z + gy * wy.z + gz * wz.z;
            u[q * 4 + 3] = gx * wx.w + gy * wy.w + gz * wz.w;
        }
        uint4 v;
        v.x = f16x2_of(u[0], u[1]);
        v.y = f16x2_of(u[2], u[3]);
        v.z = f16x2_of(u[4], u[5]);
        v.w = f16x2_of(u[6], u[7]);
        *(uint4*)(smu + O_US + row * U_P32 + c4 * 4) = v;
    }

    // ---- G fill: 4 pts x 256 uint4 = 1024 uint4, 2 per thread ----
    #pragma unroll
    for (int k = 0; k < 2; ++k) {
        int idx = k * 512 + t;
        int pt = idx >> 8, rem = idx & 255;
        int i = rem >> 3, c4 = rem & 7;
        uint4 v = *(const uint4*)(g_Gp + ((size_t)(p0 + pt) * 32 + i) * 32 + c4 * 4);
        *(uint4*)(smu + O_G + pt * 1280 + i * G_P32 + c4 * 4) = v;
    }

    // ---- ub packed f16x2; Bf fp32 ----
    if (t < 128) {
        int pt = t >> 5, k2 = t & 31;
        int pp = p0 + pt;
        float gx = geo[pp * 3], gy = geo[pp * 3 + 1], gz = geo[pp * 3 + 2];
        int h = 2 * k2;
        float u0 = gx * W1[h] + gy * W1[64 + h] + gz * W1[128 + h] + b1[h];
        float u1 = gx * W1[h + 1] + gy * W1[64 + h + 1] + gz * W1[128 + h + 1] + b1[h + 1];
        smu[O_UB + pt * 32 + k2] = f16x2_of(u0, u1);
    } else if (t < 256) {
        int pt = (t >> 5) & 3, i = t & 31;
        const float4* bw = (const float4*)(b2 + i * 32);
        const float4* fv = (const float4*)(feat + (size_t)(p0 + pt) * 32);
        float s = 0.f;
        #pragma unroll
        for (int j = 0; j < 8; ++j) {
            float4 w = bw[j], f = fv[j];
            s += w.x * f.x + w.y * f.y + w.z * f.z + w.w * f.w;
        }
        smf[O_BF + pt * 32 + i] = s;
    }
    __syncthreads();

    float acc[4][4][4];
    #pragma unroll
    for (int pt = 0; pt < 4; ++pt)
        #pragma unroll
        for (int n = 0; n < 4; ++n)
            acc[pt][n][0] = acc[pt][n][1] = acc[pt][n][2] = acc[pt][n][3] = 0.f;

    // ---- mainloop: 4 k16 steps ----
    #pragma unroll
    for (int s = 0; s < 4; ++s) {
        int k2L = 8 * s + tq, k2H = k2L + 4;
        int rA = (wid * 16 + g) * U_P32;
        uint32_t uGL  = smu[O_US + rA + k2L];
        uint32_t uG8L = smu[O_US + rA + 8 * U_P32 + k2L];
        uint32_t uGH  = smu[O_US + rA + k2H];
        uint32_t uG8H = smu[O_US + rA + 8 * U_P32 + k2H];
        #pragma unroll
        for (int pt = 0; pt < 4; ++pt) {
            uint32_t ubL = smu[O_UB + pt * 32 + k2L];
            uint32_t ubH = smu[O_UB + pt * 32 + k2H];
            uint32_t A0 = hmax2z(hsub2(ubL, uGL));
            uint32_t A1 = hmax2z(hsub2(ubL, uG8L));
            uint32_t A2 = hmax2z(hsub2(ubH, uGH));
            uint32_t A3 = hmax2z(hsub2(ubH, uG8H));
            const uint32_t* Gp = smu + O_G + pt * 1280;
            #pragma unroll
            for (int n = 0; n < 4; ++n) {
                uint2 b = *(const uint2*)(Gp + (n * 8 + g) * G_P32 + (4 * s + tq) * 2);
                mma_f16(acc[pt][n], A0, A1, A2, A3, b.x, b.y);
            }
        }
    }
    __syncthreads();   // Us dead -> reuse as fp32 stage

    // ---- epilogue per point: stage -> +Bf -> coalesced STG.128 ----
    float* st = smf + O_US;
    #pragma unroll
    for (int pt = 0; pt < 4; ++pt) {
        int row = wid * 16 + g;
        #pragma unroll
        for (int n = 0; n < 4; ++n) {
            int col = n * 8 + 2 * tq;
            float2 v0 = {acc[pt][n][0], acc[pt][n][1]};
            float2 v1 = {acc[pt][n][2], acc[pt][n][3]};
            *(float2*)(st + row * ST_P + col) = v0;
            *(float2*)(st + (row + 8) * ST_P + col) = v1;
        }
        __syncthreads();
        const float* bfp = smf + O_BF + pt * 32;
        int b = b0 + pt;
        #pragma unroll
        for (int it = 0; it < 4; ++it) {
            int idx = it * 512 + t;
            int r2 = idx >> 3, c4 = idx & 7;
            float4 v = *(const float4*)(st + r2 * ST_P + c4 * 4);
            float4 bf = *(const float4*)(bfp + c4 * 4);
            v.x += bf.x; v.y += bf.y; v.z += bf.z; v.w += bf.w;
            *(float4*)(out + (((size_t)(z * 256 + r2)) * 256 + b) * 32 + c4 * 4) = v;
        }
        __syncthreads();
    }
}

// ===========================================================================
extern "C" void kernel_launch(void* const* d_in, const int* in_sizes, int n_in,
                              void* d_out, int out_size) {
    const float* feat = (const float*)d_in[0];
    const float* geo  = (const float*)d_in[1];
    const float* W1   = (const float*)d_in[2];
    const float* b1   = (const float*)d_in[3];
    const float* W2   = (const float*)d_in[4];
    const float* b2   = (const float*)d_in[5];
    float* out = (float*)d_out;

    cudaFuncSetAttribute(pair_kernel, cudaFuncAttributeMaxDynamicSharedMemorySize,
                         SMF_U32 * 4);

    pre_G<<<dim3(32, 8), 256>>>(feat, W2);
    pair_kernel<<<256, 512, SMF_U32 * 4>>>(feat, geo, W1, b1, b2, out);
}

// round 17
// speedup vs baseline: 1.8081x; 1.0694x over previous
#include <cuda_runtime.h>
#include <cstdint>

#define NPTS 1024

// Scratch: packed fp16x2 G fragments, interleaved [p][i][32] u32.
// slot 2*(s*4+tq)+0 = b0 (k2 = 8s+tq), slot 2*(s*4+tq)+1 = b1 (k2 = 8s+tq+4)
__device__ uint32_t g_Gp[NPTS * 32 * 32];

// ===========================================================================
// helpers
// ===========================================================================
__device__ __forceinline__ uint32_t f16x2_of(float lo, float hi) {
    uint32_t r;
    asm("cvt.rn.f16x2.f32 %0, %1, %2;" : "=r"(r) : "f"(hi), "f"(lo));
    return r;
}
__device__ __forceinline__ uint32_t hsub2(uint32_t a, uint32_t b) {
    uint32_t r;
    asm("sub.rn.f16x2 %0, %1, %2;" : "=r"(r) : "r"(a), "r"(b));
    return r;
}
__device__ __forceinline__ uint32_t hmax2z(uint32_t a) {
    uint32_t r;
    asm("max.f16x2 %0, %1, %2;" : "=r"(r) : "r"(a), "r"(0u));
    return r;
}
__device__ __forceinline__ void mma_f16(float* c, uint32_t a0, uint32_t a1,
                                        uint32_t a2, uint32_t a3,
                                        uint32_t b0, uint32_t b1) {
    asm("mma.sync.aligned.m16n8k16.row.col.f32.f16.f16.f32 "
        "{%0,%1,%2,%3},{%4,%5,%6,%7},{%8,%9},{%0,%1,%2,%3};"
        : "+f"(c[0]), "+f"(c[1]), "+f"(c[2]), "+f"(c[3])
        : "r"(a0), "r"(a1), "r"(a2), "r"(a3), "r"(b0), "r"(b1));
}

// ===========================================================================
// pre_G (grid 16x8 = 128 blocks, single wave): thread tile 8p x 8e.
//   G[p][i][h] = sum_j W2[h][i*32+j]*feat[p][j] -> packed fp16x2, interleaved
//   via lane^8 shuffle, contiguous uint4 stores.
// ===========================================================================
#define FS_PAD 33
__global__ void __launch_bounds__(256) pre_G(
    const float* __restrict__ feat, const float* __restrict__ W2) {
    int bx = blockIdx.x, by = blockIdx.y;
    int t = threadIdx.x;

    int pbase = bx * 64;
    int i0g = by * 4;
    int pg = t & 7, eg = t >> 3;
    int p0 = pg * 8, e0 = eg * 8;

    __shared__ float Fs[64 * FS_PAD];
    __shared__ float Ws[32][264];

    #pragma unroll
    for (int k = 0; k < 8; ++k) {
        int idx = t + k * 256;
        int p = idx >> 5, j = idx & 31;
        Fs[p * FS_PAD + j] = feat[(size_t)(pbase + p) * 32 + j];
    }
    {
        int lane = t & 31, w = t >> 5;
        int j4 = lane & 7, sub = lane >> 3;
        #pragma unroll
        for (int q = 0; q < 8; ++q) {
            int pidx = w * 32 + q * 4 + sub;
            int il = pidx >> 6, h = pidx & 63;
            float4 v = ((const float4*)W2)[((size_t)h * 1024 + (i0g + il) * 32) / 4 + j4];
            int e = il * 64 + h;
            Ws[j4 * 4 + 0][e] = v.x;
            Ws[j4 * 4 + 1][e] = v.y;
            Ws[j4 * 4 + 2][e] = v.z;
            Ws[j4 * 4 + 3][e] = v.w;
        }
    }
    __syncthreads();

    ulonglong2 acc[8][2];
    #pragma unroll
    for (int r = 0; r < 8; ++r) {
        acc[r][0].x = acc[r][0].y = 0ull;
        acc[r][1].x = acc[r][1].y = 0ull;
    }
    #pragma unroll 8
    for (int j = 0; j < 32; ++j) {
        ulonglong2 w0 = *(const ulonglong2*)&Ws[j][e0];
        ulonglong2 w1 = *(const ulonglong2*)&Ws[j][e0 + 4];
        #pragma unroll
        for (int r = 0; r < 8; ++r) {
            float f = Fs[(p0 + r) * FS_PAD + j];
            unsigned long long s;
            unsigned int fb = __float_as_uint(f);
            asm("mov.b64 %0, {%1, %1};" : "=l"(s) : "r"(fb));
            asm("fma.rn.f32x2 %0, %1, %2, %0;" : "+l"(acc[r][0].x) : "l"(s), "l"(w0.x));
            asm("fma.rn.f32x2 %0, %1, %2, %0;" : "+l"(acc[r][0].y) : "l"(s), "l"(w0.y));
            asm("fma.rn.f32x2 %0, %1, %2, %0;" : "+l"(acc[r][1].x) : "l"(s), "l"(w1.x));
            asm("fma.rn.f32x2 %0, %1, %2, %0;" : "+l"(acc[r][1].y) : "l"(s), "l"(w1.y));
        }
    }

    // epilogue: fp16x2 pack + lane^8 interleave -> contiguous uint4 per r.
    int i = i0g + (eg >> 3);
    int s = (eg & 7) >> 1, half = eg & 1;
    #pragma unroll
    for (int r = 0; r < 8; ++r) {
        int p = pbase + p0 + r;
        uint4 vh;
        {
            float lo, hi;
            lo = __uint_as_float((uint32_t)acc[r][0].x);
            hi = __uint_as_float((uint32_t)(acc[r][0].x >> 32));
            vh.x = f16x2_of(lo, hi);
            lo = __uint_as_float((uint32_t)acc[r][0].y);
            hi = __uint_as_float((uint32_t)(acc[r][0].y >> 32));
            vh.y = f16x2_of(lo, hi);
            lo = __uint_as_float((uint32_t)acc[r][1].x);
            hi = __uint_as_float((uint32_t)(acc[r][1].x >> 32));
            vh.z = f16x2_of(lo, hi);
            lo = __uint_as_float((uint32_t)acc[r][1].y);
            hi = __uint_as_float((uint32_t)(acc[r][1].y >> 32));
            vh.w = f16x2_of(lo, hi);
        }
        uint4 pr;
        pr.x = __shfl_xor_sync(0xffffffffu, vh.x, 8);
        pr.y = __shfl_xor_sync(0xffffffffu, vh.y, 8);
        pr.z = __shfl_xor_sync(0xffffffffu, vh.z, 8);
        pr.w = __shfl_xor_sync(0xffffffffu, vh.w, 8);
        size_t o = ((size_t)p * 32 + i) * 32 + 8 * s;
        if (!half) {
            uint4 w0 = {vh.x, pr.x, vh.y, pr.y};
            *(uint4*)(g_Gp + o) = w0;
        } else {
            uint4 w1 = {pr.z, vh.z, pr.w, vh.w};
            *(uint4*)(g_Gp + o + 4) = w1;
        }
    }
}

// ===========================================================================
// pair_kernel: 8 points/block in two groups of 4, 512 threads, 128 blocks
// (SINGLE WAVE). Us packed fp16x2 shared by both groups; dedicated fp32
// stage region (Us stays live). A-build = sub.rn.f16x2 + max.f16x2.
// ===========================================================================
#define U_P32 36
#define G_P32 40
#define ST_P  36
#define O_US  0                    // 256*36 = 9216 u32 (packed f16x2 Us)
#define O_ST  9216                 // 9216 u32 (fp32 stage, 256 rows x 36)
#define O_G   18432                // 4*1280 = 5120
#define O_UB  (O_G + 5120)         // 4*32 u32 (current group's packed ub)
#define O_BF  (O_UB + 128)         // 4*32 f32
#define SMF_U32 (O_BF + 128)       // 23808 u32 = 95232 B

__global__ void __launch_bounds__(512, 1) pair_kernel(
    const float* __restrict__ feat, const float* __restrict__ geo,
    const float* __restrict__ W1, const float* __restrict__ b1,
    const float* __restrict__ b2, float* __restrict__ out) {
    extern __shared__ uint32_t smu[];
    float* smf = (float*)smu;
    int p0 = blockIdx.x * 8;
    int z = p0 >> 8, b0 = p0 & 255;
    int t = threadIdx.x, lane = t & 31, wid = t >> 5;   // wid 0..15
    int g = lane >> 2, tq = lane & 3;

    // ---- Us16 fill (once for both groups): 256 rows x 8 uint4 ----
    #pragma unroll
    for (int it = 0; it < 4; ++it) {
        int idx = it * 512 + t;
        int row = idx >> 3, c4 = idx & 7;
        int pp = z * 256 + row;
        float gx = geo[pp * 3], gy = geo[pp * 3 + 1], gz = geo[pp * 3 + 2];
        int h = c4 * 8;
        float u[8];
        #pragma unroll
        for (int q = 0; q < 2; ++q) {
            float4 wx = *(const float4*)(W1 + h + q * 4);
            float4 wy = *(const float4*)(W1 + 64 + h + q * 4);
            float4 wz = *(const float4*)(W1 + 128 + h + q * 4);
            u[q * 4 + 0] = gx * wx.x + gy * wy.x + gz * wz.x;
            u[q * 4 + 1] = gx * wx.y + gy * wy.y + gz * wz.y;
            u[q * 4 + 2] = gx * wx.z + gy * wy.z + gz * wz.z;
            u[q * 4 + 3] = gx * wx.w + gy * wy.w + gz * wz.w;
        }
        uint4 v;
        v.x = f16x2_of(u[0], u[1]);
        v.y = f16x2_of(u[2], u[3]);
        v.z = f16x2_of(u[4], u[5]);
        v.w = f16x2_of(u[6], u[7]);
        *(uint4*)(smu + O_US + row * U_P32 + c4 * 4) = v;
    }

    #pragma unroll
    for (int grp = 0; grp < 2; ++grp) {
        int p0g = p0 + grp * 4;

        // ---- group fills: G (2 uint4/thread), packed ub, Bf ----
        #pragma unroll
        for (int k = 0; k < 2; ++k) {
            int idx = k * 512 + t;
            int pt = idx >> 8, rem = idx & 255;
            int i = rem >> 3, c4 = rem & 7;
            uint4 v = *(const uint4*)(g_Gp + ((size_t)(p0g + pt) * 32 + i) * 32 + c4 * 4);
            *(uint4*)(smu + O_G + pt * 1280 + i * G_P32 + c4 * 4) = v;
        }
        if (t < 128) {
            int pt = t >> 5, k2 = t & 31;
            int pp = p0g + pt;
            float gx = geo[pp * 3], gy = geo[pp * 3 + 1], gz = geo[pp * 3 + 2];
            int h = 2 * k2;
            float u0 = gx * W1[h] + gy * W1[64 + h] + gz * W1[128 + h] + b1[h];
            float u1 = gx * W1[h + 1] + gy * W1[64 + h + 1] + gz * W1[128 + h + 1] + b1[h + 1];
            smu[O_UB + pt * 32 + k2] = f16x2_of(u0, u1);
        } else if (t < 256) {
            int pt = (t >> 5) & 3, i = t & 31;
            const float4* bw = (const float4*)(b2 + i * 32);
            const float4* fv = (const float4*)(feat + (size_t)(p0g + pt) * 32);
            float s = 0.f;
            #pragma unroll
            for (int j = 0; j < 8; ++j) {
                float4 w = bw[j], f = fv[j];
                s += w.x * f.x + w.y * f.y + w.z * f.z + w.w * f.w;
            }
            smf[O_BF + pt * 32 + i] = s;
        }
        __syncthreads();

        float acc[4][4][4];
        #pragma unroll
        for (int pt = 0; pt < 4; ++pt)
            #pragma unroll
            for (int n = 0; n < 4; ++n)
                acc[pt][n][0] = acc[pt][n][1] = acc[pt][n][2] = acc[pt][n][3] = 0.f;

        // ---- mainloop: 4 k16 steps ----
        #pragma unroll
        for (int s = 0; s < 4; ++s) {
            int k2L = 8 * s + tq, k2H = k2L + 4;
            int rA = (wid * 16 + g) * U_P32;
            uint32_t uGL  = smu[O_US + rA + k2L];
            uint32_t uG8L = smu[O_US + rA + 8 * U_P32 + k2L];
            uint32_t uGH  = smu[O_US + rA + k2H];
            uint32_t uG8H = smu[O_US + rA + 8 * U_P32 + k2H];
            #pragma unroll
            for (int pt = 0; pt < 4; ++pt) {
                uint32_t ubL = smu[O_UB + pt * 32 + k2L];
                uint32_t ubH = smu[O_UB + pt * 32 + k2H];
                uint32_t A0 = hmax2z(hsub2(ubL, uGL));
                uint32_t A1 = hmax2z(hsub2(ubL, uG8L));
                uint32_t A2 = hmax2z(hsub2(ubH, uGH));
                uint32_t A3 = hmax2z(hsub2(ubH, uG8H));
                const uint32_t* Gp = smu + O_G + pt * 1280;
                #pragma unroll
                for (int n = 0; n < 4; ++n) {
                    uint2 b = *(const uint2*)(Gp + (n * 8 + g) * G_P32 + (4 * s + tq) * 2);
                    mma_f16(acc[pt][n], A0, A1, A2, A3, b.x, b.y);
                }
            }
        }
        __syncthreads();   // mainloop done; G/UB reusable next group, stage free

        // ---- epilogue per point: stage -> +Bf -> coalesced STG.128 ----
        float* st = smf + O_ST;
        #pragma unroll
        for (int pt = 0; pt < 4; ++pt) {
            int row = wid * 16 + g;
            #pragma unroll
            for (int n = 0; n < 4; ++n) {
                int col = n * 8 + 2 * tq;
                float2 v0 = {acc[pt][n][0], acc[pt][n][1]};
                float2 v1 = {acc[pt][n][2], acc[pt][n][3]};
                *(float2*)(st + row * ST_P + col) = v0;
                *(float2*)(st + (row + 8) * ST_P + col) = v1;
            }
            __syncthreads();
            const float* bfp = smf + O_BF + pt * 32;
            int b = b0 + grp * 4 + pt;
            #pragma unroll
            for (int it = 0; it < 4; ++it) {
                int idx = it * 512 + t;
                int r2 = idx >> 3, c4 = idx & 7;
                float4 v = *(const float4*)(st + r2 * ST_P + c4 * 4);
                float4 bf = *(const float4*)(bfp + c4 * 4);
                v.x += bf.x; v.y += bf.y; v.z += bf.z; v.w += bf.w;
                *(float4*)(out + (((size_t)(z * 256 + r2)) * 256 + b) * 32 + c4 * 4) = v;
            }
            __syncthreads();
        }
    }
}

// ===========================================================================
extern "C" void kernel_launch(void* const* d_in, const int* in_sizes, int n_in,
                              void* d_out, int out_size) {
    const float* feat = (const float*)d_in[0];
    const float* geo  = (const float*)d_in[1];
    const float* W1   = (const float*)d_in[2];
    const float* b1   = (const float*)d_in[3];
    const float* W2   = (const float*)d_in[4];
    const float* b2   = (const float*)d_in[5];
    float* out = (float*)d_out;

    cudaFuncSetAttribute(pair_kernel, cudaFuncAttributeMaxDynamicSharedMemorySize,
                         SMF_U32 * 4);

    pre_G<<<dim3(16, 8), 256>>>(feat, W2);
    pair_kernel<<<128, 512, SMF_U32 * 4>>>(feat, geo, W1, b1, b2, out);
}